// round 1
// baseline (speedup 1.0000x reference)
#include <cuda_runtime.h>
#include <math.h>

#define SEQ    4096
#define DMODEL 1024
#define NH     16
#define NKV    4
#define DHEAD  64
#define KVDIM  (NKV * DHEAD)   // 256

// ---------------------------------------------------------------------------
// Scratch (allocation-free: __device__ globals)
// ---------------------------------------------------------------------------
__device__ float g_q  [SEQ * DMODEL];   // 16 MB
__device__ float g_k  [SEQ * KVDIM];    //  4 MB
__device__ float g_v  [SEQ * KVDIM];    //  4 MB
__device__ float g_att[SEQ * DMODEL];   // 16 MB
__device__ float g_invfreq[DHEAD / 2];

// ---------------------------------------------------------------------------
// inv_freq table (correctly rounded via double pow, matches fp32 reference
// values to <=1 ulp)
// ---------------------------------------------------------------------------
__global__ void invfreq_kernel() {
    int i = threadIdx.x;
    if (i < DHEAD / 2) {
        double e = (double)(2 * i) / (double)DHEAD;
        g_invfreq[i] = (float)(1.0 / pow(10000.0, e));
    }
}

// ---------------------------------------------------------------------------
// GEMM: C[M,N] = A[M,K] @ B[N,K]^T   (both operands K-contiguous, row-major)
// 128x128 tile, BK=16, 256 threads, 8x8 per-thread microtile.
// All problem dims are multiples of 128/16 -> no bounds checks.
// ---------------------------------------------------------------------------
__global__ __launch_bounds__(256) void gemm_nt_kernel(
    const float* __restrict__ A, const float* __restrict__ B,
    float* __restrict__ C, int M, int N, int K)
{
    __shared__ float As[16][132];   // [k][m], padded
    __shared__ float Bs[16][132];   // [k][n], padded

    const int tid = threadIdx.x;
    const int bm = blockIdx.y * 128;
    const int bn = blockIdx.x * 128;
    const int tx = tid & 15;
    const int ty = tid >> 4;

    float acc[8][8];
#pragma unroll
    for (int i = 0; i < 8; i++)
#pragma unroll
        for (int j = 0; j < 8; j++) acc[i][j] = 0.f;

    for (int k0 = 0; k0 < K; k0 += 16) {
#pragma unroll
        for (int t = 0; t < 2; t++) {
            int f   = tid + t * 256;      // 0..511
            int row = f >> 2;             // 0..127
            int ks  = (f & 3) * 4;        // 0,4,8,12
            float4 a = *(const float4*)(A + (size_t)(bm + row) * K + k0 + ks);
            As[ks + 0][row] = a.x; As[ks + 1][row] = a.y;
            As[ks + 2][row] = a.z; As[ks + 3][row] = a.w;
            float4 b = *(const float4*)(B + (size_t)(bn + row) * K + k0 + ks);
            Bs[ks + 0][row] = b.x; Bs[ks + 1][row] = b.y;
            Bs[ks + 2][row] = b.z; Bs[ks + 3][row] = b.w;
        }
        __syncthreads();

#pragma unroll
        for (int kk = 0; kk < 16; kk++) {
            float a[8], b[8];
            *(float4*)(a)     = *(const float4*)&As[kk][ty * 8];
            *(float4*)(a + 4) = *(const float4*)&As[kk][ty * 8 + 4];
            *(float4*)(b)     = *(const float4*)&Bs[kk][tx * 8];
            *(float4*)(b + 4) = *(const float4*)&Bs[kk][tx * 8 + 4];
#pragma unroll
            for (int i = 0; i < 8; i++)
#pragma unroll
                for (int j = 0; j < 8; j++) acc[i][j] += a[i] * b[j];
        }
        __syncthreads();
    }

#pragma unroll
    for (int i = 0; i < 8; i++) {
        float* cr = C + (size_t)(bm + ty * 8 + i) * N + bn + tx * 8;
        *(float4*)(cr)     = make_float4(acc[i][0], acc[i][1], acc[i][2], acc[i][3]);
        *(float4*)(cr + 4) = make_float4(acc[i][4], acc[i][5], acc[i][6], acc[i][7]);
    }
}

// ---------------------------------------------------------------------------
// RoPE (in place on g_q, g_k). One thread per (pos, head, pair).
// ---------------------------------------------------------------------------
__global__ void rope_kernel(float* __restrict__ q, float* __restrict__ k)
{
    const int nq = SEQ * NH * 32;
    const int nk = SEQ * NKV * 32;
    int idx = blockIdx.x * blockDim.x + threadIdx.x;
    if (idx >= nq + nk) return;

    float* base;
    int s, i;
    if (idx < nq) {
        i = idx & 31;
        int t = idx >> 5;       // s * NH + h
        int h = t & (NH - 1);
        s = t >> 4;
        base = q + (size_t)s * DMODEL + h * DHEAD;
    } else {
        int j = idx - nq;
        i = j & 31;
        int t = j >> 5;         // s * NKV + h
        int h = t & (NKV - 1);
        s = t >> 2;
        base = k + (size_t)s * KVDIM + h * DHEAD;
    }
    float ang = (float)s * g_invfreq[i];
    float sn, cs;
    sincosf(ang, &sn, &cs);
    float t1 = base[i];
    float t2 = base[i + 32];
    base[i]      = t1 * cs - t2 * sn;
    base[i + 32] = t1 * sn + t2 * cs;
}

// ---------------------------------------------------------------------------
// Causal GQA flash attention, fp32. 64 query rows x 64 key cols per tile.
// grid = (SEQ/64, NH). 256 threads: tx=tid&15 (4 cols each), ty=tid>>4 (4 rows).
// Row reductions span 16 lanes of a half-warp (shfl_xor 1,2,4,8).
// ---------------------------------------------------------------------------
__global__ __launch_bounds__(256) void attn_kernel(
    const float* __restrict__ Q, const float* __restrict__ K,
    const float* __restrict__ V, float* __restrict__ O)
{
    __shared__ float q_s [64][64];   // [d][r]
    __shared__ float kp_s[64][64];   // K tile as [d][c]; reused as P [c][r]
    __shared__ float v_s [64][64];   // [c][d]

    const int tid = threadIdx.x;
    const int qt  = (int)gridDim.x - 1 - (int)blockIdx.x;  // heavy blocks first
    const int h   = blockIdx.y;
    const int kvh = h >> 2;
    const int qbase = qt * 64;

    const int tx = tid & 15;
    const int ty = tid >> 4;
    const int r0 = ty * 4;
    const int c0 = tx * 4;

    // Load Q tile transposed into q_s[d][r]
    {
        const int r  = tid >> 2;
        const int ds = (tid & 3) * 16;
        const float* src = Q + (size_t)(qbase + r) * DMODEL + h * DHEAD + ds;
#pragma unroll
        for (int i = 0; i < 4; i++) {
            float4 t = *(const float4*)(src + 4 * i);
            q_s[ds + 4 * i + 0][r] = t.x;
            q_s[ds + 4 * i + 1][r] = t.y;
            q_s[ds + 4 * i + 2][r] = t.z;
            q_s[ds + 4 * i + 3][r] = t.w;
        }
    }

    float o[4][4];
    float m[4], l[4];
#pragma unroll
    for (int i = 0; i < 4; i++) {
        m[i] = -1e30f; l[i] = 0.f;
#pragma unroll
        for (int j = 0; j < 4; j++) o[i][j] = 0.f;
    }

    for (int kt = 0; kt <= qt; kt++) {
        const int kbase = kt * 64;

        // Load K (transposed -> kp_s[d][c]) and V (direct -> v_s[c][d])
        {
            const int c  = tid >> 2;
            const int ds = (tid & 3) * 16;
            const float* ksrc = K + (size_t)(kbase + c) * KVDIM + kvh * DHEAD + ds;
            const float* vsrc = V + (size_t)(kbase + c) * KVDIM + kvh * DHEAD + ds;
#pragma unroll
            for (int i = 0; i < 4; i++) {
                float4 t = *(const float4*)(ksrc + 4 * i);
                kp_s[ds + 4 * i + 0][c] = t.x;
                kp_s[ds + 4 * i + 1][c] = t.y;
                kp_s[ds + 4 * i + 2][c] = t.z;
                kp_s[ds + 4 * i + 3][c] = t.w;
                float4 u = *(const float4*)(vsrc + 4 * i);
                *(float4*)&v_s[c][ds + 4 * i] = u;
            }
        }
        __syncthreads();

        // Scores: s[i][j] = sum_d q[r0+i][d] * k[c0+j][d]
        float s[4][4];
#pragma unroll
        for (int i = 0; i < 4; i++)
#pragma unroll
            for (int j = 0; j < 4; j++) s[i][j] = 0.f;

#pragma unroll 16
        for (int d = 0; d < 64; d++) {
            float a[4], b[4];
            *(float4*)a = *(const float4*)&q_s[d][r0];
            *(float4*)b = *(const float4*)&kp_s[d][c0];
#pragma unroll
            for (int i = 0; i < 4; i++)
#pragma unroll
                for (int j = 0; j < 4; j++) s[i][j] += a[i] * b[j];
        }

        // Causal mask on the diagonal tile (matches ref's +(-1e9): exp -> 0)
        if (kt == qt) {
#pragma unroll
            for (int i = 0; i < 4; i++)
#pragma unroll
                for (int j = 0; j < 4; j++)
                    if (c0 + j > r0 + i) s[i][j] = -1e9f;
        }

        // Online softmax update (all 16 lanes of a half-warp share ty -> 4 rows)
#pragma unroll
        for (int i = 0; i < 4; i++) {
            float mt = fmaxf(fmaxf(s[i][0], s[i][1]), fmaxf(s[i][2], s[i][3]));
#pragma unroll
            for (int off = 1; off < 16; off <<= 1)
                mt = fmaxf(mt, __shfl_xor_sync(0xffffffffu, mt, off));
            float mn = fmaxf(m[i], mt);
            float sc = __expf(m[i] - mn);
            l[i] *= sc;
            o[i][0] *= sc; o[i][1] *= sc; o[i][2] *= sc; o[i][3] *= sc;
            float sum = 0.f;
#pragma unroll
            for (int j = 0; j < 4; j++) { s[i][j] = __expf(s[i][j] - mn); sum += s[i][j]; }
#pragma unroll
            for (int off = 1; off < 16; off <<= 1)
                sum += __shfl_xor_sync(0xffffffffu, sum, off);
            l[i] += sum;
            m[i] = mn;
        }
        __syncthreads();   // all reads of kp_s (K) complete

        // Store P transposed into kp_s[c][r]
#pragma unroll
        for (int i = 0; i < 4; i++)
#pragma unroll
            for (int j = 0; j < 4; j++)
                kp_s[c0 + j][r0 + i] = s[i][j];
        __syncthreads();

        // O[i][dc] += sum_c P[r0+i][c] * V[c][c0+dc]
#pragma unroll 16
        for (int c = 0; c < 64; c++) {
            float a[4], b[4];
            *(float4*)a = *(const float4*)&kp_s[c][r0];
            *(float4*)b = *(const float4*)&v_s[c][c0];
#pragma unroll
            for (int i = 0; i < 4; i++)
#pragma unroll
                for (int j = 0; j < 4; j++) o[i][j] += a[i] * b[j];
        }
        __syncthreads();   // PV reads done before next tile overwrites smem
    }

    // Epilogue: normalize and store (thread owns rows r0..r0+3, dcols c0..c0+3)
#pragma unroll
    for (int i = 0; i < 4; i++) {
        float inv = 1.0f / l[i];
        float4 t = make_float4(o[i][0] * inv, o[i][1] * inv,
                               o[i][2] * inv, o[i][3] * inv);
        *(float4*)(O + (size_t)(qbase + r0 + i) * DMODEL + h * DHEAD + c0) = t;
    }
}

// ---------------------------------------------------------------------------
// Launch: inputs in metadata order: x, mask, wq, wk, wv, wo. Mask is the
// deterministic causal tril (-1e9) -> implemented directly, input unused.
// ---------------------------------------------------------------------------
extern "C" void kernel_launch(void* const* d_in, const int* in_sizes, int n_in,
                              void* d_out, int out_size)
{
    const float* x  = (const float*)d_in[0];
    const float* wq = (const float*)d_in[2];
    const float* wk = (const float*)d_in[3];
    const float* wv = (const float*)d_in[4];
    const float* wo = (const float*)d_in[5];
    float* out = (float*)d_out;

    float *pq, *pk, *pv, *pa;
    cudaGetSymbolAddress((void**)&pq, g_q);
    cudaGetSymbolAddress((void**)&pk, g_k);
    cudaGetSymbolAddress((void**)&pv, g_v);
    cudaGetSymbolAddress((void**)&pa, g_att);

    invfreq_kernel<<<1, 32>>>();

    gemm_nt_kernel<<<dim3(DMODEL / 128, SEQ / 128), 256>>>(x, wq, pq, SEQ, DMODEL, DMODEL);
    gemm_nt_kernel<<<dim3(KVDIM  / 128, SEQ / 128), 256>>>(x, wk, pk, SEQ, KVDIM,  DMODEL);
    gemm_nt_kernel<<<dim3(KVDIM  / 128, SEQ / 128), 256>>>(x, wv, pv, SEQ, KVDIM,  DMODEL);

    const int nrope = SEQ * NH * 32 + SEQ * NKV * 32;
    rope_kernel<<<(nrope + 255) / 256, 256>>>(pq, pk);

    attn_kernel<<<dim3(SEQ / 64, NH), 256>>>(pq, pk, pv, pa);

    gemm_nt_kernel<<<dim3(DMODEL / 128, SEQ / 128), 256>>>(pa, wo, out, SEQ, DMODEL, DMODEL);
}

// round 3
// speedup vs baseline: 3.1586x; 3.1586x over previous
#include <cuda_runtime.h>
#include <cuda_fp16.h>
#include <math.h>
#include <stdint.h>

#define SEQ    4096
#define DMODEL 1024
#define NH     16
#define NKV    4
#define DHEAD  64
#define KVDIM  (NKV * DHEAD)   // 256

// ---------------------------------------------------------------------------
// Scratch (__device__ globals; allocation-free)
// ---------------------------------------------------------------------------
__device__ __half g_xhi [SEQ * DMODEL],   g_xlo [SEQ * DMODEL];
__device__ __half g_wqhi[DMODEL * DMODEL], g_wqlo[DMODEL * DMODEL];
__device__ __half g_wkhi[KVDIM * DMODEL],  g_wklo[KVDIM * DMODEL];
__device__ __half g_wvhi[KVDIM * DMODEL],  g_wvlo[KVDIM * DMODEL];
__device__ __half g_wohi[DMODEL * DMODEL], g_wolo[DMODEL * DMODEL];
__device__ float  g_qf  [SEQ * DMODEL];
__device__ float  g_kf  [SEQ * KVDIM];
__device__ __half g_qhi [SEQ * DMODEL],   g_qlo [SEQ * DMODEL];
__device__ __half g_khi [SEQ * KVDIM],    g_klo [SEQ * KVDIM];
__device__ __half g_vh  [SEQ * KVDIM];
__device__ __half g_ahi [SEQ * DMODEL],   g_alo [SEQ * DMODEL];
__device__ float  g_invfreq[DHEAD / 2];

// ---------------------------------------------------------------------------
// PTX helpers
// ---------------------------------------------------------------------------
__device__ __forceinline__ uint32_t smem_u32(const void* p) {
    uint32_t a;
    asm("{ .reg .u64 t; cvta.to.shared.u64 t, %1; cvt.u32.u64 %0, t; }"
        : "=r"(a) : "l"(p));
    return a;
}
__device__ __forceinline__ void ldm_x4(uint32_t* r, uint32_t a) {
    asm volatile("ldmatrix.sync.aligned.m8n8.x4.shared.b16 {%0,%1,%2,%3}, [%4];"
                 : "=r"(r[0]), "=r"(r[1]), "=r"(r[2]), "=r"(r[3]) : "r"(a));
}
__device__ __forceinline__ void ldm_x2(uint32_t* r, uint32_t a) {
    asm volatile("ldmatrix.sync.aligned.m8n8.x2.shared.b16 {%0,%1}, [%2];"
                 : "=r"(r[0]), "=r"(r[1]) : "r"(a));
}
__device__ __forceinline__ void ldm_x2t(uint32_t* r, uint32_t a) {
    asm volatile("ldmatrix.sync.aligned.m8n8.x2.trans.shared.b16 {%0,%1}, [%2];"
                 : "=r"(r[0]), "=r"(r[1]) : "r"(a));
}
__device__ __forceinline__ void mma16816(float* d, const uint32_t* a,
                                         const uint32_t* b, const float* c) {
    asm volatile(
        "mma.sync.aligned.m16n8k16.row.col.f32.f16.f16.f32 "
        "{%0,%1,%2,%3}, {%4,%5,%6,%7}, {%8,%9}, {%10,%11,%12,%13};"
        : "=f"(d[0]), "=f"(d[1]), "=f"(d[2]), "=f"(d[3])
        : "r"(a[0]), "r"(a[1]), "r"(a[2]), "r"(a[3]), "r"(b[0]), "r"(b[1]),
          "f"(c[0]), "f"(c[1]), "f"(c[2]), "f"(c[3]));
}

__device__ __forceinline__ void split2(float v, __half& hi, __half& lo) {
    hi = __float2half_rn(v);
    lo = __float2half_rn(v - __half2float(hi));
}

// ---------------------------------------------------------------------------
// Small kernels
// ---------------------------------------------------------------------------
__global__ void invfreq_kernel() {
    int i = threadIdx.x;
    if (i < DHEAD / 2) {
        double e = (double)(2 * i) / (double)DHEAD;
        g_invfreq[i] = (float)(1.0 / pow(10000.0, e));
    }
}

__global__ void f2h_split_kernel(const float* __restrict__ src,
                                 __half* __restrict__ hi, __half* __restrict__ lo, int n) {
    int i = (blockIdx.x * blockDim.x + threadIdx.x) * 4;
    if (i < n) {
        float4 v = *(const float4*)(src + i);
        __half h0, l0, h1, l1, h2, l2, h3, l3;
        split2(v.x, h0, l0); split2(v.y, h1, l1);
        split2(v.z, h2, l2); split2(v.w, h3, l3);
        *(__half2*)(hi + i)     = __halves2half2(h0, h1);
        *(__half2*)(hi + i + 2) = __halves2half2(h2, h3);
        *(__half2*)(lo + i)     = __halves2half2(l0, l1);
        *(__half2*)(lo + i + 2) = __halves2half2(l2, l3);
    }
}

// RoPE from fp32 q/k, emit split-fp16 pairs. One thread per (pos, head, i<32).
__global__ void rope_split_kernel(
    const float* __restrict__ qf, const float* __restrict__ kf,
    __half* __restrict__ qhi, __half* __restrict__ qlo,
    __half* __restrict__ khi, __half* __restrict__ klo)
{
    const int nq = SEQ * NH * 32;
    const int nk = SEQ * NKV * 32;
    int idx = blockIdx.x * blockDim.x + threadIdx.x;
    if (idx >= nq + nk) return;

    const float* srcb;
    __half *dhib, *dlob;
    size_t off;
    int s, i;
    if (idx < nq) {
        i = idx & 31;
        int t = idx >> 5;
        int h = t & (NH - 1);
        s = t >> 4;
        off = (size_t)s * DMODEL + h * DHEAD;
        srcb = qf; dhib = qhi; dlob = qlo;
    } else {
        int j = idx - nq;
        i = j & 31;
        int t = j >> 5;
        int h = t & (NKV - 1);
        s = t >> 2;
        off = (size_t)s * KVDIM + h * DHEAD;
        srcb = kf; dhib = khi; dlob = klo;
    }
    float ang = (float)s * g_invfreq[i];
    float sn, cs;
    sincosf(ang, &sn, &cs);
    float t1 = srcb[off + i];
    float t2 = srcb[off + i + 32];
    float v1 = t1 * cs - t2 * sn;
    float v2 = t1 * sn + t2 * cs;
    __half h1, l1, h2, l2;
    split2(v1, h1, l1);
    split2(v2, h2, l2);
    dhib[off + i] = h1;      dlob[off + i] = l1;
    dhib[off + i + 32] = h2; dlob[off + i + 32] = l2;
}

// ---------------------------------------------------------------------------
// Split GEMM: C = (Ahi+Alo) @ (Bhi+Blo)^T ~= AhiBhi + AhiBlo + AloBhi.
// 128x128 tile, BK=32, 8 warps (2x4), warp = 64x32.
// OUT: 0 = float, 1 = half single.
// ---------------------------------------------------------------------------
template<int OUT>
__global__ __launch_bounds__(256) void gemm_split_kernel(
    const __half* __restrict__ Ahi, const __half* __restrict__ Alo,
    const __half* __restrict__ Bhi, const __half* __restrict__ Blo,
    void* __restrict__ Cv, int M, int N, int K)
{
    __shared__ __half Ash[128][40], Asl[128][40];
    __shared__ __half Bsh[128][40], Bsl[128][40];

    const int tid  = threadIdx.x;
    const int lane = tid & 31;
    const int wid  = tid >> 5;
    const int wr   = wid >> 2;
    const int wc   = wid & 3;
    const int bm   = blockIdx.y * 128;
    const int bn   = blockIdx.x * 128;

    float acc[4][4][4];
#pragma unroll
    for (int mt = 0; mt < 4; mt++)
#pragma unroll
        for (int nt = 0; nt < 4; nt++)
#pragma unroll
            for (int r = 0; r < 4; r++) acc[mt][nt][r] = 0.f;

    for (int k0 = 0; k0 < K; k0 += 32) {
#pragma unroll
        for (int t = 0; t < 2; t++) {
            int f   = tid + t * 256;
            int row = f >> 2;
            int seg = (f & 3) * 8;
            size_t ga = (size_t)(bm + row) * K + k0 + seg;
            size_t gb = (size_t)(bn + row) * K + k0 + seg;
            *(float4*)&Ash[row][seg] = *(const float4*)(Ahi + ga);
            *(float4*)&Asl[row][seg] = *(const float4*)(Alo + ga);
            *(float4*)&Bsh[row][seg] = *(const float4*)(Bhi + gb);
            *(float4*)&Bsl[row][seg] = *(const float4*)(Blo + gb);
        }
        __syncthreads();

#pragma unroll
        for (int kc = 0; kc < 2; kc++) {
            const int kk = kc * 16;
            uint32_t afh[4][4], afl[4][4];
#pragma unroll
            for (int mt = 0; mt < 4; mt++) {
                int r0 = wr * 64 + mt * 16;
                int rr = (lane < 16) ? r0 + lane : r0 + lane - 16;
                int cc = (lane < 16) ? kk : kk + 8;
                ldm_x4(afh[mt], smem_u32(&Ash[rr][cc]));
                ldm_x4(afl[mt], smem_u32(&Asl[rr][cc]));
            }
#pragma unroll
            for (int nt = 0; nt < 4; nt++) {
                int c0 = wc * 32 + nt * 8;
                int rr = (lane < 8) ? c0 + lane : (lane < 16) ? c0 + lane - 8 : c0;
                int cc = (lane < 8) ? kk : (lane < 16) ? kk + 8 : kk;
                uint32_t bfh[2], bfl[2];
                ldm_x2(bfh, smem_u32(&Bsh[rr][cc]));
                ldm_x2(bfl, smem_u32(&Bsl[rr][cc]));
#pragma unroll
                for (int mt = 0; mt < 4; mt++) {
                    mma16816(acc[mt][nt], afh[mt], bfh, acc[mt][nt]);
                    mma16816(acc[mt][nt], afh[mt], bfl, acc[mt][nt]);
                    mma16816(acc[mt][nt], afl[mt], bfh, acc[mt][nt]);
                }
            }
        }
        __syncthreads();
    }

#pragma unroll
    for (int mt = 0; mt < 4; mt++) {
#pragma unroll
        for (int nt = 0; nt < 4; nt++) {
            int r = bm + wr * 64 + mt * 16 + (lane >> 2);
            int c = bn + wc * 32 + nt * 8 + (lane & 3) * 2;
            if (OUT == 1) {
                __half* C = (__half*)Cv;
                *(__half2*)(C + (size_t)r * N + c)       = __floats2half2_rn(acc[mt][nt][0], acc[mt][nt][1]);
                *(__half2*)(C + (size_t)(r + 8) * N + c) = __floats2half2_rn(acc[mt][nt][2], acc[mt][nt][3]);
            } else {
                float* C = (float*)Cv;
                *(float2*)(C + (size_t)r * N + c)       = make_float2(acc[mt][nt][0], acc[mt][nt][1]);
                *(float2*)(C + (size_t)(r + 8) * N + c) = make_float2(acc[mt][nt][2], acc[mt][nt][3]);
            }
        }
    }
}

// ---------------------------------------------------------------------------
// Flash attention. Br=128 (8 warps x 16 rows), Bc=64, D=64, causal GQA.
// S = QK^T via 3-term fp16 split (fp32-class accuracy). P fp16, V fp16.
// Output written as split hi/lo pair. Dynamic smem (~63KB).
// ---------------------------------------------------------------------------
__global__ __launch_bounds__(256) void attn_split_kernel(
    const __half* __restrict__ Qhi, const __half* __restrict__ Qlo,
    const __half* __restrict__ Khi, const __half* __restrict__ Klo,
    const __half* __restrict__ V,
    __half* __restrict__ Ohi, __half* __restrict__ Olo)
{
    extern __shared__ __half sm[];
    __half (*Qsh)[72] = (__half(*)[72])(sm);
    __half (*Qsl)[72] = (__half(*)[72])(sm + 128 * 72);
    __half (*Ksh)[72] = (__half(*)[72])(sm + 2 * 128 * 72);
    __half (*Ksl)[72] = (__half(*)[72])(sm + 2 * 128 * 72 + 64 * 72);
    __half (*Vs) [72] = (__half(*)[72])(sm + 2 * 128 * 72 + 2 * 64 * 72);

    const int tid  = threadIdx.x;
    const int lane = tid & 31;
    const int wid  = tid >> 5;
    const int qt   = (int)gridDim.x - 1 - (int)blockIdx.x;  // heavy first
    const int h    = blockIdx.y;
    const int kvh  = h >> 2;
    const int qbase = qt * 128;
    const int r0    = wid * 16;

    // Load Q tile (hi+lo)
#pragma unroll
    for (int t = 0; t < 4; t++) {
        int f   = tid + t * 256;
        int row = f >> 3;
        int seg = (f & 7) * 8;
        size_t g = (size_t)(qbase + row) * DMODEL + h * DHEAD + seg;
        *(float4*)&Qsh[row][seg] = *(const float4*)(Qhi + g);
        *(float4*)&Qsl[row][seg] = *(const float4*)(Qlo + g);
    }

    float o[8][4];
#pragma unroll
    for (int dt = 0; dt < 8; dt++)
#pragma unroll
        for (int r = 0; r < 4; r++) o[dt][r] = 0.f;
    float m0 = -1e30f, m1 = -1e30f, l0 = 0.f, l1 = 0.f;

    const int ntiles = (qbase + 128) / 64;

    for (int kt = 0; kt < ntiles; kt++) {
        const int kbase = kt * 64;
#pragma unroll
        for (int t = 0; t < 2; t++) {
            int f   = tid + t * 256;
            int row = f >> 3;
            int seg = (f & 7) * 8;
            size_t g = (size_t)(kbase + row) * KVDIM + kvh * DHEAD + seg;
            *(float4*)&Ksh[row][seg] = *(const float4*)(Khi + g);
            *(float4*)&Ksl[row][seg] = *(const float4*)(Klo + g);
            *(float4*)&Vs[row][seg]  = *(const float4*)(V + g);
        }
        __syncthreads();

        // S = Q@K^T, 3-term split
        float s[8][4];
#pragma unroll
        for (int nt = 0; nt < 8; nt++)
#pragma unroll
            for (int r = 0; r < 4; r++) s[nt][r] = 0.f;

#pragma unroll
        for (int kc = 0; kc < 4; kc++) {
            const int kk = kc * 16;
            uint32_t afh[4], afl[4];
            {
                int rr = (lane < 16) ? r0 + lane : r0 + lane - 16;
                int cc = (lane < 16) ? kk : kk + 8;
                ldm_x4(afh, smem_u32(&Qsh[rr][cc]));
                ldm_x4(afl, smem_u32(&Qsl[rr][cc]));
            }
#pragma unroll
            for (int nt = 0; nt < 8; nt++) {
                int rr = (lane < 8) ? nt * 8 + lane : (lane < 16) ? nt * 8 + lane - 8 : nt * 8;
                int cc = (lane < 8) ? kk : (lane < 16) ? kk + 8 : kk;
                uint32_t bfh[2], bfl[2];
                ldm_x2(bfh, smem_u32(&Ksh[rr][cc]));
                ldm_x2(bfl, smem_u32(&Ksl[rr][cc]));
                mma16816(s[nt], afh, bfh, s[nt]);
                mma16816(s[nt], afh, bfl, s[nt]);
                mma16816(s[nt], afl, bfh, s[nt]);
            }
        }

        // Causal mask
        if (kbase + 63 > qbase + r0) {
            const int ra = qbase + r0 + (lane >> 2);
            const int rb = ra + 8;
#pragma unroll
            for (int nt = 0; nt < 8; nt++) {
                const int c = kbase + nt * 8 + (lane & 3) * 2;
                if (c     > ra) s[nt][0] = -1e9f;
                if (c + 1 > ra) s[nt][1] = -1e9f;
                if (c     > rb) s[nt][2] = -1e9f;
                if (c + 1 > rb) s[nt][3] = -1e9f;
            }
        }

        // Online softmax
        float tm0 = -1e30f, tm1 = -1e30f;
#pragma unroll
        for (int nt = 0; nt < 8; nt++) {
            tm0 = fmaxf(tm0, fmaxf(s[nt][0], s[nt][1]));
            tm1 = fmaxf(tm1, fmaxf(s[nt][2], s[nt][3]));
        }
#pragma unroll
        for (int off = 1; off < 4; off <<= 1) {
            tm0 = fmaxf(tm0, __shfl_xor_sync(0xffffffffu, tm0, off));
            tm1 = fmaxf(tm1, __shfl_xor_sync(0xffffffffu, tm1, off));
        }
        float mn0 = fmaxf(m0, tm0), mn1 = fmaxf(m1, tm1);
        float sc0 = __expf(m0 - mn0), sc1 = __expf(m1 - mn1);
        l0 *= sc0; l1 *= sc1;
#pragma unroll
        for (int dt = 0; dt < 8; dt++) {
            o[dt][0] *= sc0; o[dt][1] *= sc0;
            o[dt][2] *= sc1; o[dt][3] *= sc1;
        }
        float sum0 = 0.f, sum1 = 0.f;
        uint32_t ph[8][2];
#pragma unroll
        for (int nt = 0; nt < 8; nt++) {
            float e0 = __expf(s[nt][0] - mn0);
            float e1 = __expf(s[nt][1] - mn0);
            float e2 = __expf(s[nt][2] - mn1);
            float e3 = __expf(s[nt][3] - mn1);
            sum0 += e0 + e1; sum1 += e2 + e3;
            __half2 lo = __floats2half2_rn(e0, e1);
            __half2 hi = __floats2half2_rn(e2, e3);
            ph[nt][0] = *(uint32_t*)&lo;
            ph[nt][1] = *(uint32_t*)&hi;
        }
#pragma unroll
        for (int off = 1; off < 4; off <<= 1) {
            sum0 += __shfl_xor_sync(0xffffffffu, sum0, off);
            sum1 += __shfl_xor_sync(0xffffffffu, sum1, off);
        }
        l0 += sum0; l1 += sum1;
        m0 = mn0; m1 = mn1;

        // O += P @ V
#pragma unroll
        for (int kc = 0; kc < 4; kc++) {
            uint32_t af[4] = { ph[2 * kc][0], ph[2 * kc][1],
                               ph[2 * kc + 1][0], ph[2 * kc + 1][1] };
#pragma unroll
            for (int dt = 0; dt < 8; dt++) {
                uint32_t bf[2];
                int rr = (lane < 16) ? kc * 16 + lane : kc * 16;
                ldm_x2t(bf, smem_u32(&Vs[rr][dt * 8]));
                mma16816(o[dt], af, bf, o[dt]);
            }
        }
        __syncthreads();
    }

    // Epilogue: normalized output, split into hi/lo fp16
    const float inv0 = 1.0f / l0, inv1 = 1.0f / l1;
    const int ra = qbase + r0 + (lane >> 2);
    const int cc = (lane & 3) * 2;
#pragma unroll
    for (int dt = 0; dt < 8; dt++) {
        float v0 = o[dt][0] * inv0, v1 = o[dt][1] * inv0;
        float v2 = o[dt][2] * inv1, v3 = o[dt][3] * inv1;
        __half h0, l0h, h1, l1h, h2, l2h, h3, l3h;
        split2(v0, h0, l0h); split2(v1, h1, l1h);
        split2(v2, h2, l2h); split2(v3, h3, l3h);
        size_t ga = (size_t)ra * DMODEL + h * DHEAD + dt * 8 + cc;
        size_t gb = (size_t)(ra + 8) * DMODEL + h * DHEAD + dt * 8 + cc;
        *(__half2*)(Ohi + ga) = __halves2half2(h0, h1);
        *(__half2*)(Olo + ga) = __halves2half2(l0h, l1h);
        *(__half2*)(Ohi + gb) = __halves2half2(h2, h3);
        *(__half2*)(Olo + gb) = __halves2half2(l2h, l3h);
    }
}

// ---------------------------------------------------------------------------
// Launch. Inputs: x, mask, wq, wk, wv, wo (mask deterministic; in-kernel).
// ---------------------------------------------------------------------------
extern "C" void kernel_launch(void* const* d_in, const int* in_sizes, int n_in,
                              void* d_out, int out_size)
{
    const float* x  = (const float*)d_in[0];
    const float* wq = (const float*)d_in[2];
    const float* wk = (const float*)d_in[3];
    const float* wv = (const float*)d_in[4];
    const float* wo = (const float*)d_in[5];
    float* out = (float*)d_out;

    __half *xhi, *xlo, *wqhi, *wqlo, *wkhi, *wklo, *wvhi, *wvlo, *wohi, *wolo;
    __half *qhi, *qlo, *khi, *klo, *vh, *ahi, *alo;
    float *qf, *kf;
    cudaGetSymbolAddress((void**)&xhi,  g_xhi);  cudaGetSymbolAddress((void**)&xlo,  g_xlo);
    cudaGetSymbolAddress((void**)&wqhi, g_wqhi); cudaGetSymbolAddress((void**)&wqlo, g_wqlo);
    cudaGetSymbolAddress((void**)&wkhi, g_wkhi); cudaGetSymbolAddress((void**)&wklo, g_wklo);
    cudaGetSymbolAddress((void**)&wvhi, g_wvhi); cudaGetSymbolAddress((void**)&wvlo, g_wvlo);
    cudaGetSymbolAddress((void**)&wohi, g_wohi); cudaGetSymbolAddress((void**)&wolo, g_wolo);
    cudaGetSymbolAddress((void**)&qhi,  g_qhi);  cudaGetSymbolAddress((void**)&qlo,  g_qlo);
    cudaGetSymbolAddress((void**)&khi,  g_khi);  cudaGetSymbolAddress((void**)&klo,  g_klo);
    cudaGetSymbolAddress((void**)&vh,   g_vh);
    cudaGetSymbolAddress((void**)&ahi,  g_ahi);  cudaGetSymbolAddress((void**)&alo,  g_alo);
    cudaGetSymbolAddress((void**)&qf,   g_qf);   cudaGetSymbolAddress((void**)&kf,   g_kf);

    static bool attr_set = false;
    if (!attr_set) {
        cudaFuncSetAttribute(attn_split_kernel,
                             cudaFuncAttributeMaxDynamicSharedMemorySize, 65536);
        attr_set = true;
    }

    invfreq_kernel<<<1, 32>>>();

    f2h_split_kernel<<<(SEQ * DMODEL / 4 + 255) / 256, 256>>>(x,  xhi,  xlo,  SEQ * DMODEL);
    f2h_split_kernel<<<(DMODEL * DMODEL / 4 + 255) / 256, 256>>>(wq, wqhi, wqlo, DMODEL * DMODEL);
    f2h_split_kernel<<<(KVDIM * DMODEL / 4 + 255) / 256, 256>>>(wk, wkhi, wklo, KVDIM * DMODEL);
    f2h_split_kernel<<<(KVDIM * DMODEL / 4 + 255) / 256, 256>>>(wv, wvhi, wvlo, KVDIM * DMODEL);
    f2h_split_kernel<<<(DMODEL * DMODEL / 4 + 255) / 256, 256>>>(wo, wohi, wolo, DMODEL * DMODEL);

    gemm_split_kernel<0><<<dim3(DMODEL / 128, SEQ / 128), 256>>>(xhi, xlo, wqhi, wqlo, qf, SEQ, DMODEL, DMODEL);
    gemm_split_kernel<0><<<dim3(KVDIM  / 128, SEQ / 128), 256>>>(xhi, xlo, wkhi, wklo, kf, SEQ, KVDIM,  DMODEL);
    gemm_split_kernel<1><<<dim3(KVDIM  / 128, SEQ / 128), 256>>>(xhi, xlo, wvhi, wvlo, vh, SEQ, KVDIM,  DMODEL);

    const int nrope = SEQ * NH * 32 + SEQ * NKV * 32;
    rope_split_kernel<<<(nrope + 255) / 256, 256>>>(qf, kf, qhi, qlo, khi, klo);

    attn_split_kernel<<<dim3(SEQ / 128, NH), 256, 65536>>>(qhi, qlo, khi, klo, vh, ahi, alo);

    gemm_split_kernel<0><<<dim3(DMODEL / 128, SEQ / 128), 256>>>(ahi, alo, wohi, wolo, out, SEQ, DMODEL, DMODEL);
}

// round 5
// speedup vs baseline: 3.8793x; 1.2282x over previous
#include <cuda_runtime.h>
#include <cuda_fp16.h>
#include <math.h>
#include <stdint.h>

#define SEQ    4096
#define DMODEL 1024
#define NH     16
#define NKV    4
#define DHEAD  64
#define KVDIM  (NKV * DHEAD)   // 256
#define NFUSE  (DMODEL + 2 * KVDIM)  // 1536 fused QKV output width

// ---------------------------------------------------------------------------
// Scratch (__device__ globals; allocation-free)
// ---------------------------------------------------------------------------
__device__ __align__(16) __half g_xhi  [SEQ * DMODEL],  g_xlo  [SEQ * DMODEL];
__device__ __align__(16) __half g_wfh  [NFUSE * DMODEL], g_wfl [NFUSE * DMODEL]; // fused wq|wk|wv
__device__ __align__(16) __half g_wohi [DMODEL * DMODEL];
__device__ __align__(16) float  g_c    [SEQ * NFUSE];    // fused QKV output (fp32)
__device__ __align__(16) __half g_qhi  [SEQ * DMODEL],  g_qlo  [SEQ * DMODEL];
__device__ __align__(16) __half g_khi  [SEQ * KVDIM],   g_klo  [SEQ * KVDIM];
__device__ __align__(16) __half g_vh   [SEQ * KVDIM];
__device__ __align__(16) __half g_ahi  [SEQ * DMODEL],  g_alo  [SEQ * DMODEL];
__device__ float g_invfreq[DHEAD / 2];

// ---------------------------------------------------------------------------
// PTX helpers
// ---------------------------------------------------------------------------
__device__ __forceinline__ uint32_t smem_u32(const void* p) {
    uint32_t a;
    asm("{ .reg .u64 t; cvta.to.shared.u64 t, %1; cvt.u32.u64 %0, t; }"
        : "=r"(a) : "l"(p));
    return a;
}
__device__ __forceinline__ void ldm_x4(uint32_t* r, uint32_t a) {
    asm volatile("ldmatrix.sync.aligned.m8n8.x4.shared.b16 {%0,%1,%2,%3}, [%4];"
                 : "=r"(r[0]), "=r"(r[1]), "=r"(r[2]), "=r"(r[3]) : "r"(a));
}
__device__ __forceinline__ void ldm_x2(uint32_t* r, uint32_t a) {
    asm volatile("ldmatrix.sync.aligned.m8n8.x2.shared.b16 {%0,%1}, [%2];"
                 : "=r"(r[0]), "=r"(r[1]) : "r"(a));
}
__device__ __forceinline__ void ldm_x2t(uint32_t* r, uint32_t a) {
    asm volatile("ldmatrix.sync.aligned.m8n8.x2.trans.shared.b16 {%0,%1}, [%2];"
                 : "=r"(r[0]), "=r"(r[1]) : "r"(a));
}
__device__ __forceinline__ void mma16816(float* d, const uint32_t* a,
                                         const uint32_t* b, const float* c) {
    asm volatile(
        "mma.sync.aligned.m16n8k16.row.col.f32.f16.f16.f32 "
        "{%0,%1,%2,%3}, {%4,%5,%6,%7}, {%8,%9}, {%10,%11,%12,%13};"
        : "=f"(d[0]), "=f"(d[1]), "=f"(d[2]), "=f"(d[3])
        : "r"(a[0]), "r"(a[1]), "r"(a[2]), "r"(a[3]), "r"(b[0]), "r"(b[1]),
          "f"(c[0]), "f"(c[1]), "f"(c[2]), "f"(c[3]));
}
__device__ __forceinline__ void split2(float v, __half& hi, __half& lo) {
    hi = __float2half_rn(v);
    lo = __float2half_rn(v - __half2float(hi));
}
__device__ __forceinline__ void cp16(uint32_t dst, const void* src) {
    asm volatile("cp.async.cg.shared.global [%0], [%1], 16;" :: "r"(dst), "l"(src));
}
#define CP_COMMIT() asm volatile("cp.async.commit_group;" ::: "memory")
#define CP_WAIT(n)  asm volatile("cp.async.wait_group %0;" :: "n"(n) : "memory")

// ---------------------------------------------------------------------------
// Small kernels
// ---------------------------------------------------------------------------
__global__ void invfreq_kernel() {
    int i = threadIdx.x;
    if (i < DHEAD / 2) {
        double e = (double)(2 * i) / (double)DHEAD;
        g_invfreq[i] = (float)(1.0 / pow(10000.0, e));
    }
}

__global__ void f2h_split_kernel(const float* __restrict__ src,
                                 __half* __restrict__ hi, __half* __restrict__ lo, int n) {
    int i = (blockIdx.x * blockDim.x + threadIdx.x) * 4;
    if (i < n) {
        float4 v = *(const float4*)(src + i);
        __half h0, l0, h1, l1, h2, l2, h3, l3;
        split2(v.x, h0, l0); split2(v.y, h1, l1);
        split2(v.z, h2, l2); split2(v.w, h3, l3);
        *(__half2*)(hi + i)     = __halves2half2(h0, h1);
        *(__half2*)(hi + i + 2) = __halves2half2(h2, h3);
        *(__half2*)(lo + i)     = __halves2half2(l0, l1);
        *(__half2*)(lo + i + 2) = __halves2half2(l2, l3);
    }
}

__global__ void f2h_kernel(const float* __restrict__ src, __half* __restrict__ dst, int n) {
    int i = (blockIdx.x * blockDim.x + threadIdx.x) * 4;
    if (i < n) {
        float4 v = *(const float4*)(src + i);
        __half2* d = (__half2*)(dst + i);
        d[0] = __floats2half2_rn(v.x, v.y);
        d[1] = __floats2half2_rn(v.z, v.w);
    }
}

// RoPE from fused fp32 C (stride NFUSE): cols [0,1024)=q, [1024,1280)=k.
__global__ void rope_split_kernel(
    const float* __restrict__ C,
    __half* __restrict__ qhi, __half* __restrict__ qlo,
    __half* __restrict__ khi, __half* __restrict__ klo)
{
    const int nq = SEQ * NH * 32;
    const int nk = SEQ * NKV * 32;
    int idx = blockIdx.x * blockDim.x + threadIdx.x;
    if (idx >= nq + nk) return;

    const float* src;
    __half *dhi, *dlo;
    int s, i;
    if (idx < nq) {
        i = idx & 31;
        int t = idx >> 5;
        int h = t & (NH - 1);
        s = t >> 4;
        src = C + (size_t)s * NFUSE + h * DHEAD;
        dhi = g_qhi + (size_t)s * DMODEL + h * DHEAD;
        dlo = g_qlo + (size_t)s * DMODEL + h * DHEAD;
    } else {
        int j = idx - nq;
        i = j & 31;
        int t = j >> 5;
        int h = t & (NKV - 1);
        s = t >> 2;
        src = C + (size_t)s * NFUSE + DMODEL + h * DHEAD;
        dhi = g_khi + (size_t)s * KVDIM + h * DHEAD;
        dlo = g_klo + (size_t)s * KVDIM + h * DHEAD;
    }
    float ang = (float)s * g_invfreq[i];
    float sn, cs;
    sincosf(ang, &sn, &cs);
    float t1 = src[i];
    float t2 = src[i + 32];
    float v1 = t1 * cs - t2 * sn;
    float v2 = t1 * sn + t2 * cs;
    __half h1, l1, h2, l2;
    split2(v1, h1, l1);
    split2(v2, h2, l2);
    dhi[i] = h1;      dlo[i] = l1;
    dhi[i + 32] = h2; dlo[i + 32] = l2;
}

// Pack V columns [1280,1536) of fused C into half.
__global__ void vpack_kernel(const float* __restrict__ C, __half* __restrict__ vh) {
    int i = (blockIdx.x * blockDim.x + threadIdx.x) * 4;
    if (i < SEQ * KVDIM) {
        int s = i >> 8;           // / KVDIM
        int c = i & (KVDIM - 1);
        float4 v = *(const float4*)(C + (size_t)s * NFUSE + DMODEL + KVDIM + c);
        __half2* d = (__half2*)(vh + i);
        d[0] = __floats2half2_rn(v.x, v.y);
        d[1] = __floats2half2_rn(v.z, v.w);
    }
}

// ---------------------------------------------------------------------------
// Split GEMM, cp.async 2-stage pipelined. C = split-product of A @ B^T.
// TERMS=3: AhiBhi + AhiBlo + AloBhi. TERMS=2: AhiBhi + AloBhi (B fp16-quantized).
// 128x128 tile, BK=32, 8 warps (2x4), warp = 64x32. C fp32.
// Stage layout (halfs): Ah[128][40] Al[128][40] Bh[128][40] (Bl[128][40]).
// ---------------------------------------------------------------------------
template<int TERMS>
__global__ __launch_bounds__(256) void gemm_split_pipe(
    const __half* __restrict__ Ahi, const __half* __restrict__ Alo,
    const __half* __restrict__ Bhi, const __half* __restrict__ Blo,
    float* __restrict__ C, int M, int N, int K)
{
    constexpr int NARR = (TERMS == 3) ? 4 : 3;
    constexpr int ARR_H = 128 * 40;          // halfs per array
    constexpr int STAGE_H = NARR * ARR_H;    // halfs per stage

    extern __shared__ __half smp[];

    const int tid  = threadIdx.x;
    const int lane = tid & 31;
    const int wid  = tid >> 5;
    const int wr   = wid >> 2;
    const int wc   = wid & 3;
    const int bm   = blockIdx.y * 128;
    const int bn   = blockIdx.x * 128;

    const __half* gp[4];
    gp[0] = Ahi + (size_t)bm * K;
    gp[1] = Alo + (size_t)bm * K;
    gp[2] = Bhi + (size_t)bn * K;
    gp[3] = (TERMS == 3) ? (Blo + (size_t)bn * K) : nullptr;

    const int nch = K / 32;

    auto load_chunk = [&](int c) {
        __half* sb = smp + (c & 1) * STAGE_H;
        const int k0 = c * 32;
#pragma unroll
        for (int j = 0; j < NARR * 2; j++) {
            const int arr = j >> 1;               // compile-time per unrolled j
            const int e   = tid + (j & 1) * 256;  // 0..511
            const int row = e >> 2;
            const int seg = e & 3;
            uint32_t dst = smem_u32(sb + arr * ARR_H + row * 40 + seg * 8);
            cp16(dst, gp[arr] + (size_t)row * K + k0 + seg * 8);
        }
        CP_COMMIT();
    };

    float acc[4][4][4];
#pragma unroll
    for (int mt = 0; mt < 4; mt++)
#pragma unroll
        for (int nt = 0; nt < 4; nt++)
#pragma unroll
            for (int r = 0; r < 4; r++) acc[mt][nt][r] = 0.f;

    load_chunk(0);

    for (int c = 0; c < nch; c++) {
        if (c + 1 < nch) { load_chunk(c + 1); CP_WAIT(1); }
        else             { CP_WAIT(0); }
        __syncthreads();

        __half (*Ash)[40] = (__half(*)[40])(smp + (c & 1) * STAGE_H);
        __half (*Asl)[40] = (__half(*)[40])(smp + (c & 1) * STAGE_H + ARR_H);
        __half (*Bsh)[40] = (__half(*)[40])(smp + (c & 1) * STAGE_H + 2 * ARR_H);
        __half (*Bsl)[40] = (__half(*)[40])(smp + (c & 1) * STAGE_H + 3 * ARR_H);

#pragma unroll
        for (int kc = 0; kc < 2; kc++) {
            const int kk = kc * 16;
            uint32_t afh[4][4], afl[4][4];
#pragma unroll
            for (int mt = 0; mt < 4; mt++) {
                int r0 = wr * 64 + mt * 16;
                int rr = (lane < 16) ? r0 + lane : r0 + lane - 16;
                int cc = (lane < 16) ? kk : kk + 8;
                ldm_x4(afh[mt], smem_u32(&Ash[rr][cc]));
                ldm_x4(afl[mt], smem_u32(&Asl[rr][cc]));
            }
#pragma unroll
            for (int nt = 0; nt < 4; nt++) {
                int c0 = wc * 32 + nt * 8;
                int rr = (lane < 8) ? c0 + lane : (lane < 16) ? c0 + lane - 8 : c0;
                int cc = (lane < 8) ? kk : (lane < 16) ? kk + 8 : kk;
                uint32_t bfh[2], bfl[2];
                ldm_x2(bfh, smem_u32(&Bsh[rr][cc]));
                if (TERMS == 3) ldm_x2(bfl, smem_u32(&Bsl[rr][cc]));
#pragma unroll
                for (int mt = 0; mt < 4; mt++) {
                    mma16816(acc[mt][nt], afh[mt], bfh, acc[mt][nt]);
                    if (TERMS == 3) mma16816(acc[mt][nt], afh[mt], bfl, acc[mt][nt]);
                    mma16816(acc[mt][nt], afl[mt], bfh, acc[mt][nt]);
                }
            }
        }
        __syncthreads();
    }

#pragma unroll
    for (int mt = 0; mt < 4; mt++) {
#pragma unroll
        for (int nt = 0; nt < 4; nt++) {
            int r = bm + wr * 64 + mt * 16 + (lane >> 2);
            int c = bn + wc * 32 + nt * 8 + (lane & 3) * 2;
            *(float2*)(C + (size_t)r * N + c)       = make_float2(acc[mt][nt][0], acc[mt][nt][1]);
            *(float2*)(C + (size_t)(r + 8) * N + c) = make_float2(acc[mt][nt][2], acc[mt][nt][3]);
        }
    }
}

// ---------------------------------------------------------------------------
// Flash attention, cp.async double-buffered KV. Br=128, Bc=64, D=64, causal
// GQA, 3-term QK split, fp16 P/V, split hi/lo output.
// Dynamic smem (halfs): Qh[128][72] Ql[128][72] | 2 stages x (Kh,Kl,V)[64][72].
// ---------------------------------------------------------------------------
__global__ __launch_bounds__(256) void attn_split_kernel(
    const __half* __restrict__ Qhi, const __half* __restrict__ Qlo,
    const __half* __restrict__ Khi, const __half* __restrict__ Klo,
    const __half* __restrict__ V,
    __half* __restrict__ Ohi, __half* __restrict__ Olo)
{
    constexpr int QARR = 128 * 72;           // halfs
    constexpr int KARR = 64 * 72;
    constexpr int KSTAGE = 3 * KARR;

    extern __shared__ __half sm[];
    __half (*Qsh)[72] = (__half(*)[72])(sm);
    __half (*Qsl)[72] = (__half(*)[72])(sm + QARR);
    __half* kvb = sm + 2 * QARR;

    const int tid  = threadIdx.x;
    const int lane = tid & 31;
    const int wid  = tid >> 5;
    const int qt   = (int)gridDim.x - 1 - (int)blockIdx.x;  // heavy first
    const int h    = blockIdx.y;
    const int kvh  = h >> 2;
    const int qbase = qt * 128;
    const int r0    = wid * 16;

    const __half* gkv[3] = { Khi, Klo, V };

    auto load_kv = [&](int kt) {
        const int kbase = kt * 64;
        __half* sb = kvb + (kt & 1) * KSTAGE;
#pragma unroll
        for (int j = 0; j < 6; j++) {
            const int arr = j >> 1;
            const int e   = tid + (j & 1) * 256;  // 0..511
            const int row = e >> 3;               // 0..63
            const int seg = e & 7;
            uint32_t dst = smem_u32(sb + arr * KARR + row * 72 + seg * 8);
            cp16(dst, gkv[arr] + (size_t)(kbase + row) * KVDIM + kvh * DHEAD + seg * 8);
        }
        CP_COMMIT();
    };

    // Q tile (plain loads)
#pragma unroll
    for (int t = 0; t < 4; t++) {
        int f   = tid + t * 256;
        int row = f >> 3;
        int seg = (f & 7) * 8;
        size_t g = (size_t)(qbase + row) * DMODEL + h * DHEAD + seg;
        *(float4*)&Qsh[row][seg] = *(const float4*)(Qhi + g);
        *(float4*)&Qsl[row][seg] = *(const float4*)(Qlo + g);
    }

    float o[8][4];
#pragma unroll
    for (int dt = 0; dt < 8; dt++)
#pragma unroll
        for (int r = 0; r < 4; r++) o[dt][r] = 0.f;
    float m0 = -1e30f, m1 = -1e30f, l0 = 0.f, l1 = 0.f;

    const int ntiles = (qbase + 128) / 64;
    load_kv(0);

    for (int kt = 0; kt < ntiles; kt++) {
        const int kbase = kt * 64;
        if (kt + 1 < ntiles) { load_kv(kt + 1); CP_WAIT(1); }
        else                 { CP_WAIT(0); }
        __syncthreads();

        __half (*Ksh)[72] = (__half(*)[72])(kvb + (kt & 1) * KSTAGE);
        __half (*Ksl)[72] = (__half(*)[72])(kvb + (kt & 1) * KSTAGE + KARR);
        __half (*Vs)[72]  = (__half(*)[72])(kvb + (kt & 1) * KSTAGE + 2 * KARR);

        const bool active = (kbase <= qbase + r0 + 15);
        if (active) {
            float s[8][4];
#pragma unroll
            for (int nt = 0; nt < 8; nt++)
#pragma unroll
                for (int r = 0; r < 4; r++) s[nt][r] = 0.f;

#pragma unroll
            for (int kc = 0; kc < 4; kc++) {
                const int kk = kc * 16;
                uint32_t afh[4], afl[4];
                {
                    int rr = (lane < 16) ? r0 + lane : r0 + lane - 16;
                    int cc = (lane < 16) ? kk : kk + 8;
                    ldm_x4(afh, smem_u32(&Qsh[rr][cc]));
                    ldm_x4(afl, smem_u32(&Qsl[rr][cc]));
                }
#pragma unroll
                for (int nt = 0; nt < 8; nt++) {
                    int rr = (lane < 8) ? nt * 8 + lane : (lane < 16) ? nt * 8 + lane - 8 : nt * 8;
                    int cc = (lane < 8) ? kk : (lane < 16) ? kk + 8 : kk;
                    uint32_t bfh[2], bfl[2];
                    ldm_x2(bfh, smem_u32(&Ksh[rr][cc]));
                    ldm_x2(bfl, smem_u32(&Ksl[rr][cc]));
                    mma16816(s[nt], afh, bfh, s[nt]);
                    mma16816(s[nt], afh, bfl, s[nt]);
                    mma16816(s[nt], afl, bfh, s[nt]);
                }
            }

            if (kbase + 63 > qbase + r0) {
                const int ra = qbase + r0 + (lane >> 2);
                const int rb = ra + 8;
#pragma unroll
                for (int nt = 0; nt < 8; nt++) {
                    const int c = kbase + nt * 8 + (lane & 3) * 2;
                    if (c     > ra) s[nt][0] = -1e9f;
                    if (c + 1 > ra) s[nt][1] = -1e9f;
                    if (c     > rb) s[nt][2] = -1e9f;
                    if (c + 1 > rb) s[nt][3] = -1e9f;
                }
            }

            float tm0 = -1e30f, tm1 = -1e30f;
#pragma unroll
            for (int nt = 0; nt < 8; nt++) {
                tm0 = fmaxf(tm0, fmaxf(s[nt][0], s[nt][1]));
                tm1 = fmaxf(tm1, fmaxf(s[nt][2], s[nt][3]));
            }
#pragma unroll
            for (int off = 1; off < 4; off <<= 1) {
                tm0 = fmaxf(tm0, __shfl_xor_sync(0xffffffffu, tm0, off));
                tm1 = fmaxf(tm1, __shfl_xor_sync(0xffffffffu, tm1, off));
            }
            float mn0 = fmaxf(m0, tm0), mn1 = fmaxf(m1, tm1);
            float sc0 = __expf(m0 - mn0), sc1 = __expf(m1 - mn1);
            l0 *= sc0; l1 *= sc1;
#pragma unroll
            for (int dt = 0; dt < 8; dt++) {
                o[dt][0] *= sc0; o[dt][1] *= sc0;
                o[dt][2] *= sc1; o[dt][3] *= sc1;
            }
            float sum0 = 0.f, sum1 = 0.f;
            uint32_t ph[8][2];
#pragma unroll
            for (int nt = 0; nt < 8; nt++) {
                float e0 = __expf(s[nt][0] - mn0);
                float e1 = __expf(s[nt][1] - mn0);
                float e2 = __expf(s[nt][2] - mn1);
                float e3 = __expf(s[nt][3] - mn1);
                sum0 += e0 + e1; sum1 += e2 + e3;
                __half2 lo = __floats2half2_rn(e0, e1);
                __half2 hi = __floats2half2_rn(e2, e3);
                ph[nt][0] = *(uint32_t*)&lo;
                ph[nt][1] = *(uint32_t*)&hi;
            }
#pragma unroll
            for (int off = 1; off < 4; off <<= 1) {
                sum0 += __shfl_xor_sync(0xffffffffu, sum0, off);
                sum1 += __shfl_xor_sync(0xffffffffu, sum1, off);
            }
            l0 += sum0; l1 += sum1;
            m0 = mn0; m1 = mn1;

#pragma unroll
            for (int kc = 0; kc < 4; kc++) {
                uint32_t af[4] = { ph[2 * kc][0], ph[2 * kc][1],
                                   ph[2 * kc + 1][0], ph[2 * kc + 1][1] };
#pragma unroll
                for (int dt = 0; dt < 8; dt++) {
                    uint32_t bf[2];
                    int rr = (lane < 16) ? kc * 16 + lane : kc * 16;
                    ldm_x2t(bf, smem_u32(&Vs[rr][dt * 8]));
                    mma16816(o[dt], af, bf, o[dt]);
                }
            }
        }
        __syncthreads();
    }

    const float inv0 = 1.0f / l0, inv1 = 1.0f / l1;
    const int ra = qbase + r0 + (lane >> 2);
    const int cc = (lane & 3) * 2;
#pragma unroll
    for (int dt = 0; dt < 8; dt++) {
        float v0 = o[dt][0] * inv0, v1 = o[dt][1] * inv0;
        float v2 = o[dt][2] * inv1, v3 = o[dt][3] * inv1;
        __half h0, l0h, h1, l1h, h2, l2h, h3, l3h;
        split2(v0, h0, l0h); split2(v1, h1, l1h);
        split2(v2, h2, l2h); split2(v3, h3, l3h);
        size_t ga = (size_t)ra * DMODEL + h * DHEAD + dt * 8 + cc;
        size_t gb = (size_t)(ra + 8) * DMODEL + h * DHEAD + dt * 8 + cc;
        *(__half2*)(Ohi + ga) = __halves2half2(h0, h1);
        *(__half2*)(Olo + ga) = __halves2half2(l0h, l1h);
        *(__half2*)(Ohi + gb) = __halves2half2(h2, h3);
        *(__half2*)(Olo + gb) = __halves2half2(l2h, l3h);
    }
}

// ---------------------------------------------------------------------------
// Launch. Inputs: x, mask, wq, wk, wv, wo (mask deterministic; in-kernel).
// ---------------------------------------------------------------------------
extern "C" void kernel_launch(void* const* d_in, const int* in_sizes, int n_in,
                              void* d_out, int out_size)
{
    const float* x  = (const float*)d_in[0];
    const float* wq = (const float*)d_in[2];
    const float* wk = (const float*)d_in[3];
    const float* wv = (const float*)d_in[4];
    const float* wo = (const float*)d_in[5];
    float* out = (float*)d_out;

    __half *xhi, *xlo, *wfh, *wfl, *wohi, *qhi, *qlo, *khi, *klo, *vh, *ahi, *alo;
    float *cbuf;
    cudaGetSymbolAddress((void**)&xhi,  g_xhi);  cudaGetSymbolAddress((void**)&xlo,  g_xlo);
    cudaGetSymbolAddress((void**)&wfh,  g_wfh);  cudaGetSymbolAddress((void**)&wfl,  g_wfl);
    cudaGetSymbolAddress((void**)&wohi, g_wohi);
    cudaGetSymbolAddress((void**)&qhi,  g_qhi);  cudaGetSymbolAddress((void**)&qlo,  g_qlo);
    cudaGetSymbolAddress((void**)&khi,  g_khi);  cudaGetSymbolAddress((void**)&klo,  g_klo);
    cudaGetSymbolAddress((void**)&vh,   g_vh);
    cudaGetSymbolAddress((void**)&ahi,  g_ahi);  cudaGetSymbolAddress((void**)&alo,  g_alo);
    cudaGetSymbolAddress((void**)&cbuf, g_c);

    constexpr int SMEM_G3 = 2 * 4 * 128 * 40 * 2;  // 81920 B
    constexpr int SMEM_G2 = 2 * 3 * 128 * 40 * 2;  // 61440 B
    constexpr int SMEM_AT = (2 * 128 * 72 + 2 * 3 * 64 * 72) * 2;  // 92160 B

    static bool attr_set = false;
    if (!attr_set) {
        cudaFuncSetAttribute(gemm_split_pipe<3>,
                             cudaFuncAttributeMaxDynamicSharedMemorySize, SMEM_G3);
        cudaFuncSetAttribute(gemm_split_pipe<2>,
                             cudaFuncAttributeMaxDynamicSharedMemorySize, SMEM_G2);
        cudaFuncSetAttribute(attn_split_kernel,
                             cudaFuncAttributeMaxDynamicSharedMemorySize, SMEM_AT);
        attr_set = true;
    }

    invfreq_kernel<<<1, 32>>>();

    // Splits: x, fused [wq|wk|wv] hi/lo, wo hi-only
    f2h_split_kernel<<<(SEQ * DMODEL / 4 + 255) / 256, 256>>>(x, xhi, xlo, SEQ * DMODEL);
    f2h_split_kernel<<<(DMODEL * DMODEL / 4 + 255) / 256, 256>>>(
        wq, wfh, wfl, DMODEL * DMODEL);
    f2h_split_kernel<<<(KVDIM * DMODEL / 4 + 255) / 256, 256>>>(
        wk, wfh + (size_t)DMODEL * DMODEL, wfl + (size_t)DMODEL * DMODEL, KVDIM * DMODEL);
    f2h_split_kernel<<<(KVDIM * DMODEL / 4 + 255) / 256, 256>>>(
        wv, wfh + (size_t)(DMODEL + KVDIM) * DMODEL, wfl + (size_t)(DMODEL + KVDIM) * DMODEL,
        KVDIM * DMODEL);
    f2h_kernel<<<(DMODEL * DMODEL / 4 + 255) / 256, 256>>>(wo, wohi, DMODEL * DMODEL);

    // Fused QKV projection: [4096,1024] @ [1536,1024]^T -> fp32 [4096,1536]
    gemm_split_pipe<3><<<dim3(NFUSE / 128, SEQ / 128), 256, SMEM_G3>>>(
        xhi, xlo, wfh, wfl, cbuf, SEQ, NFUSE, DMODEL);

    const int nrope = SEQ * NH * 32 + SEQ * NKV * 32;
    rope_split_kernel<<<(nrope + 255) / 256, 256>>>(cbuf, qhi, qlo, khi, klo);
    vpack_kernel<<<(SEQ * KVDIM / 4 + 255) / 256, 256>>>(cbuf, vh);

    attn_split_kernel<<<dim3(SEQ / 128, NH), 256, SMEM_AT>>>(qhi, qlo, khi, klo, vh, ahi, alo);

    // Output projection: 2-term (wo fp16-quantized)
    gemm_split_pipe<2><<<dim3(DMODEL / 128, SEQ / 128), 256, SMEM_G2>>>(
        ahi, alo, wohi, nullptr, out, SEQ, DMODEL, DMODEL);
}